// round 14
// baseline (speedup 1.0000x reference)
#include <cuda_runtime.h>
#include <cuda_bf16.h>
#include <math.h>

// Problem dims
#define BB 64
#define TT 1024
#define II 128
#define HH 256
#define YSZ (BB*TT*HH)   // 16777216

// ---------------- scratch (device globals; no allocs allowed) ----------------
__device__ float g_G[BB * TT * 512];    // gate pre-activations (x-part + bias)
__device__ float g_y1[BB * TT * HH];    // layer-1 outputs

// ---------------- f32x2 helpers ----------------
__device__ __forceinline__ unsigned long long pack2(float lo, float hi) {
    unsigned long long r;
    asm("mov.b64 %0, {%1, %2};" : "=l"(r) : "f"(lo), "f"(hi));
    return r;
}
__device__ __forceinline__ void unpack2(unsigned long long v, float& lo, float& hi) {
    asm("mov.b64 {%0, %1}, %2;" : "=f"(lo), "=f"(hi) : "l"(v));
}
__device__ __forceinline__ unsigned long long fma2(unsigned long long a, unsigned long long b,
                                                   unsigned long long c) {
    unsigned long long d;
    asm("fma.rn.f32x2 %0, %1, %2, %3;" : "=l"(d) : "l"(a), "l"(b), "l"(c));
    return d;
}
// bf16x2 (lo=w[k], hi=w[k+1]) -> f32x2 via shift/mask (2 ALU ops)
__device__ __forceinline__ unsigned long long bf2_to_f32x2(unsigned int v) {
    unsigned int lo = v << 16;
    unsigned int hi = v & 0xFFFF0000u;
    return pack2(__uint_as_float(lo), __uint_as_float(hi));
}

// ---------------- GEMM: G[m, 0:512] = A[m,:K] @ {Wf|Wc}[:K,:256] + bias -------------
#define GM_BM 128
#define GM_BK 16

__global__ void __launch_bounds__(256) gemm_gates(
    const float* __restrict__ A, int lda, int K,
    const float* __restrict__ Wf, const float* __restrict__ Wc,
    const float* __restrict__ bf, const float* __restrict__ bc,
    float* __restrict__ G)
{
    __shared__ __align__(16) float As[GM_BK][GM_BM];
    __shared__ __align__(16) float Bs[GM_BK][GM_BM];

    int nt = blockIdx.x;
    int m0 = blockIdx.y * GM_BM;
    const float* W  = (nt < 2) ? Wf : Wc;
    const float* bs = (nt < 2) ? bf : bc;
    int nbase = (nt & 1) * 128;

    int tid = threadIdx.x;
    int tx = tid & 15;
    int ty = tid >> 4;

    int arow = tid >> 1;
    int acol = (tid & 1) * 8;
    int brow = tid >> 4;
    int bcol = (tid & 15) * 8;

    unsigned long long cc[8][4];
#pragma unroll
    for (int i = 0; i < 8; i++)
#pragma unroll
        for (int j = 0; j < 4; j++) cc[i][j] = 0ull;

    const float* Aptr = &A[(size_t)(m0 + arow) * lda + acol];
    const float* Bptr = &W[(size_t)brow * 256 + nbase + bcol];

    float4 a0 = *reinterpret_cast<const float4*>(Aptr);
    float4 a1 = *reinterpret_cast<const float4*>(Aptr + 4);
    float4 b0 = *reinterpret_cast<const float4*>(Bptr);
    float4 b1 = *reinterpret_cast<const float4*>(Bptr + 4);

    for (int k0 = 0; k0 < K; k0 += GM_BK) {
        As[acol + 0][arow] = a0.x; As[acol + 1][arow] = a0.y;
        As[acol + 2][arow] = a0.z; As[acol + 3][arow] = a0.w;
        As[acol + 4][arow] = a1.x; As[acol + 5][arow] = a1.y;
        As[acol + 6][arow] = a1.z; As[acol + 7][arow] = a1.w;
        *reinterpret_cast<float4*>(&Bs[brow][bcol])     = b0;
        *reinterpret_cast<float4*>(&Bs[brow][bcol + 4]) = b1;
        __syncthreads();

        if (k0 + GM_BK < K) {
            const float* An = Aptr + (k0 + GM_BK);
            const float* Bn = Bptr + (size_t)(k0 + GM_BK) * 256;
            a0 = *reinterpret_cast<const float4*>(An);
            a1 = *reinterpret_cast<const float4*>(An + 4);
            b0 = *reinterpret_cast<const float4*>(Bn);
            b1 = *reinterpret_cast<const float4*>(Bn + 4);
        }
#pragma unroll
        for (int kk = 0; kk < GM_BK; kk++) {
            float a[8];
            *reinterpret_cast<float4*>(a)     = *reinterpret_cast<const float4*>(&As[kk][ty * 8]);
            *reinterpret_cast<float4*>(a + 4) = *reinterpret_cast<const float4*>(&As[kk][ty * 8 + 4]);
            const ulonglong2* bu2 = reinterpret_cast<const ulonglong2*>(&Bs[kk][tx * 8]);
            ulonglong2 b01 = bu2[0];
            ulonglong2 b23 = bu2[1];
            unsigned long long bp[4] = {b01.x, b01.y, b23.x, b23.y};
#pragma unroll
            for (int i = 0; i < 8; i++) {
                unsigned long long ap = pack2(a[i], a[i]);
#pragma unroll
                for (int j = 0; j < 4; j++) cc[i][j] = fma2(ap, bp[j], cc[i][j]);
            }
        }
        __syncthreads();
    }
#pragma unroll
    for (int i = 0; i < 8; i++) {
        int m = m0 + ty * 8 + i;
        float* gr = &G[(size_t)m * 512 + nt * 128 + tx * 8];
#pragma unroll
        for (int j = 0; j < 4; j++) {
            float lo, hi;
            unpack2(cc[i][j], lo, hi);
            int cl = nbase + tx * 8 + 2 * j;
            float2 st;
            st.x = lo + bs[cl];
            st.y = hi + bs[cl + 1];
            *reinterpret_cast<float2*>(&gr[2 * j]) = st;
        }
    }
}

// ---------------- Recurrent sweep: 2 batches FUSED per 2-CTA cluster ----------------
// 32 clusters x 2 CTAs; CTA rank r owns h cols [128r,128r+128) for BOTH batches.
// warp w owns local cols 8w..8w+7; lane&7 col, (lane>>3)&1 gate, lane>>4 K-half.
// Weights per thread (64 pairs of its K-half): 24 f32x2 regs + 4 f32x2 smem + 36 bf16x2 smem.
// FUSION: each weight chunk is loaded/decompressed ONCE and FMA'd into both batches'
// accumulators (independent chains -> 2x ILP, half the weight LDS per batch).
// Sync: ONE cluster barrier per step-pair (proven release/acquire for smem + DSMEM).
#define REC_THREADS 512
#define REGP 24
#define FSMP 4                                  // f32 pairs in smem (2 ulonglong2/thr)
#define BSMP 36                                 // bf16 pairs in smem (9 uint4/thr)
#define WSMF_BYTES ((FSMP/2) * 512 * 16)        // 16384
#define WSMB_BYTES ((BSMP/4) * 512 * 16)        // 73728
#define WSM_BYTES (WSMF_BYTES + WSMB_BYTES)     // 90112

__global__ void __launch_bounds__(REC_THREADS, 1) rec_kernel(
    const float* __restrict__ G, const float* __restrict__ Wf, const float* __restrict__ Wc,
    int xdim, float* __restrict__ Y, float* __restrict__ hidOut)
{
    extern __shared__ __align__(16) unsigned char smem_raw[];
    ulonglong2* wsmF = reinterpret_cast<ulonglong2*>(smem_raw);
    uint4*      wsmB = reinterpret_cast<uint4*>(smem_raw + WSMF_BYTES);

    __shared__ __align__(16) float hsmA[2 * 256];   // double-buffered h, batch A
    __shared__ __align__(16) float hsmB[2 * 256];   // double-buffered h, batch B

    int tid  = threadIdx.x;
    int cid  = blockIdx.x >> 1;             // cluster id 0..31
    int rank = blockIdx.x & 1;
    int bA   = cid * 2;                     // batches bA, bA+1
    int lane = tid & 31;
    int w    = tid >> 5;
    int isC  = (lane >> 3) & 1;
    int kh   = lane >> 4;
    int cl   = (w << 3) | (lane & 7);
    int gcol = rank * 128 + cl;
    bool writer = (lane < 8);
    const float* Wsrc = (isC ? Wc : Wf) + (size_t)xdim * 256;
    int kb = kh * 128;

    // --- weights: 24 f32x2 pairs in regs ---
    unsigned long long wreg[REGP];
#pragma unroll
    for (int i = 0; i < REGP; i++) {
        int k = kb + 2 * i;
        wreg[i] = pack2(Wsrc[(size_t)k * 256 + gcol], Wsrc[(size_t)(k + 1) * 256 + gcol]);
    }
    // --- weights: 4 f32x2 pairs in smem (2 ulonglong2/thread) ---
#pragma unroll
    for (int j = 0; j < FSMP / 2; j++) {
        int k = kb + 2 * (REGP + 2 * j);
        ulonglong2 wv;
        wv.x = pack2(Wsrc[(size_t)k * 256 + gcol],       Wsrc[(size_t)(k + 1) * 256 + gcol]);
        wv.y = pack2(Wsrc[(size_t)(k + 2) * 256 + gcol], Wsrc[(size_t)(k + 3) * 256 + gcol]);
        wsmF[j * 512 + tid] = wv;
    }
    // --- weights: 36 bf16x2 pairs in smem (9 uint4/thread) ---
#pragma unroll
    for (int j = 0; j < BSMP / 4; j++) {
        unsigned int q[4];
#pragma unroll
        for (int p = 0; p < 4; p++) {
            int k = kb + 2 * (REGP + FSMP + 4 * j + p);
            __nv_bfloat162 bb = __floats2bfloat162_rn(Wsrc[(size_t)k * 256 + gcol],
                                                      Wsrc[(size_t)(k + 1) * 256 + gcol]);
            q[p] = *reinterpret_cast<unsigned int*>(&bb);
        }
        uint4 v; v.x = q[0]; v.y = q[1]; v.z = q[2]; v.w = q[3];
        wsmB[j * 512 + tid] = v;
    }
    if (tid < 512) { hsmA[tid] = 0.0f; hsmB[tid] = 0.0f; }
    __syncthreads();
    // cluster barrier: peer smem init complete before any DSMEM traffic
    asm volatile("barrier.cluster.arrive.aligned;" ::: "memory");
    asm volatile("barrier.cluster.wait.aligned;"   ::: "memory");

    int peer = rank ^ 1;
    unsigned int hA_L = (unsigned int)__cvta_generic_to_shared(hsmA);
    unsigned int hB_L = (unsigned int)__cvta_generic_to_shared(hsmB);
    unsigned int hA_P, hB_P;
    asm("mapa.shared::cluster.u32 %0, %1, %2;" : "=r"(hA_P) : "r"(hA_L), "r"(peer));
    asm("mapa.shared::cluster.u32 %0, %1, %2;" : "=r"(hB_P) : "r"(hB_L), "r"(peer));

    const ulonglong2* hAV2 = reinterpret_cast<const ulonglong2*>(hsmA);
    const ulonglong2* hBV2 = reinterpret_cast<const ulonglong2*>(hsmB);
    int og = isC ? (256 + gcol) : gcol;
    const float* GptrA = G + (size_t)bA * TT * 512 + og;
    const float* GptrB = GptrA + (size_t)TT * 512;
    float* YrowA = Y + (size_t)bA * TT * HH;
    float* YrowB = YrowA + (size_t)TT * HH;

    float hRegA = 0.0f, hRegB = 0.0f;
    float gvA = GptrA[0], gvB = GptrB[0];

    for (int t = 0; t < TT; t++) {
        int cur = t & 1;
        float gnA = (t + 1 < TT) ? GptrA[(size_t)(t + 1) * 512] : 0.0f;
        float gnB = (t + 1 < TT) ? GptrB[(size_t)(t + 1) * 512] : 0.0f;

        unsigned long long aA0 = 0ull, aA1 = 0ull, aA2 = 0ull, aA3 = 0ull;
        unsigned long long aB0 = 0ull, aB1 = 0ull, aB2 = 0ull, aB3 = 0ull;
        int hbase = cur * 64 + kh * 32;

        // fused: register weights x both batches
#pragma unroll
        for (int i = 0; i < REGP / 2; i++) {
            ulonglong2 hvA = hAV2[hbase + i];
            ulonglong2 hvB = hBV2[hbase + i];
            aA0 = fma2(wreg[2 * i],     hvA.x, aA0);
            aB0 = fma2(wreg[2 * i],     hvB.x, aB0);
            aA1 = fma2(wreg[2 * i + 1], hvA.y, aA1);
            aB1 = fma2(wreg[2 * i + 1], hvB.y, aB1);
        }
        // fused: f32-smem weights (loaded once) x both batches
#pragma unroll
        for (int j = 0; j < FSMP / 2; j++) {
            ulonglong2 wv = wsmF[j * 512 + tid];
            ulonglong2 hvA = hAV2[hbase + REGP / 2 + j];
            ulonglong2 hvB = hBV2[hbase + REGP / 2 + j];
            aA2 = fma2(wv.x, hvA.x, aA2);
            aB2 = fma2(wv.x, hvB.x, aB2);
            aA3 = fma2(wv.y, hvA.y, aA3);
            aB3 = fma2(wv.y, hvB.y, aB3);
        }
        // fused: bf16-smem weights (loaded+decompressed once) x both batches
#pragma unroll
        for (int j = 0; j < BSMP / 4; j++) {
            uint4 wv = wsmB[j * 512 + tid];
            unsigned long long w0 = bf2_to_f32x2(wv.x);
            unsigned long long w1 = bf2_to_f32x2(wv.y);
            unsigned long long w2 = bf2_to_f32x2(wv.z);
            unsigned long long w3 = bf2_to_f32x2(wv.w);
            int hb = hbase + (REGP + FSMP) / 2 + 2 * j;
            ulonglong2 hA0 = hAV2[hb];
            ulonglong2 hA1 = hAV2[hb + 1];
            ulonglong2 hB0 = hBV2[hb];
            ulonglong2 hB1 = hBV2[hb + 1];
            aA2 = fma2(w0, hA0.x, aA2);
            aB2 = fma2(w0, hB0.x, aB2);
            aA3 = fma2(w1, hA0.y, aA3);
            aB3 = fma2(w1, hB0.y, aB3);
            aA2 = fma2(w2, hA1.x, aA2);
            aB2 = fma2(w2, hB1.x, aB2);
            aA3 = fma2(w3, hA1.y, aA3);
            aB3 = fma2(w3, hB1.y, aB3);
        }
        float sA, sB, x0, x1;
        unpack2(aA0, x0, x1); sA  = x0 + x1;
        unpack2(aA1, x0, x1); sA += x0 + x1;
        unpack2(aA2, x0, x1); sA += x0 + x1;
        unpack2(aA3, x0, x1); sA += x0 + x1;
        unpack2(aB0, x0, x1); sB  = x0 + x1;
        unpack2(aB1, x0, x1); sB += x0 + x1;
        unpack2(aB2, x0, x1); sB += x0 + x1;
        unpack2(aB3, x0, x1); sB += x0 + x1;
        // combine K-halves (lanes l, l^16) for both batches
        sA += __shfl_xor_sync(0xffffffffu, sA, 16);
        sB += __shfl_xor_sync(0xffffffffu, sB, 16);

        float preA = sA + gvA;  gvA = gnA;
        float preB = sB + gvB;  gvB = gnB;
        float actA, actB;
        if (isC) {
            float eA = __expf(2.0f * preA);
            float eB = __expf(2.0f * preB);
            actA = __fdividef(eA - 1.0f, eA + 1.0f);
            actB = __fdividef(eB - 1.0f, eB + 1.0f);
        } else {
            actA = __fdividef(1.0f, 1.0f + __expf(-preA));
            actB = __fdividef(1.0f, 1.0f + __expf(-preB));
        }
        float otherA = __shfl_xor_sync(0xffffffffu, actA, 8);   // c into f lanes
        float otherB = __shfl_xor_sync(0xffffffffu, actB, 8);

        if (writer) {
            int nxt = cur ^ 1;
            unsigned int off = (unsigned int)(nxt * 256 + gcol) * 4u;
            float fA = actA, cA = otherA;
            float hnA = cA + fA * (hRegA - cA);
            hRegA = hnA;
            hsmA[nxt * 256 + gcol] = hnA;
            asm volatile("st.shared::cluster.f32 [%0], %1;" :: "r"(hA_P + off), "f"(hnA));
            YrowA[(size_t)t * HH + gcol] = hnA;

            float fB = actB, cB = otherB;
            float hnB = cB + fB * (hRegB - cB);
            hRegB = hnB;
            hsmB[nxt * 256 + gcol] = hnB;
            asm volatile("st.shared::cluster.f32 [%0], %1;" :: "r"(hB_P + off), "f"(hnB));
            YrowB[(size_t)t * HH + gcol] = hnB;
        }
        // ONE rendezvous per step-pair: release our h stores, acquire peer's
        asm volatile("barrier.cluster.arrive.aligned;" ::: "memory");
        asm volatile("barrier.cluster.wait.aligned;"   ::: "memory");
    }

    if (writer) {
        hidOut[(size_t)bA * HH + gcol] = hRegA;
        hidOut[(size_t)(bA + 1) * HH + gcol] = hRegB;
    }
}

// ---------------- host launch ----------------
static void launch_rec(const float* G, const float* Wf, const float* Wc, int xdim,
                       float* Y, float* hid)
{
    cudaLaunchConfig_t cfg = {};
    cfg.gridDim  = dim3(BB, 1, 1);          // 64 CTAs = 32 clusters x 2
    cfg.blockDim = dim3(REC_THREADS, 1, 1);
    cfg.dynamicSmemBytes = WSM_BYTES;
    cfg.stream = 0;
    cudaLaunchAttribute attr[1];
    attr[0].id = cudaLaunchAttributeClusterDimension;
    attr[0].val.clusterDim.x = 2;
    attr[0].val.clusterDim.y = 1;
    attr[0].val.clusterDim.z = 1;
    cfg.attrs = attr;
    cfg.numAttrs = 1;
    cudaLaunchKernelEx(&cfg, rec_kernel, G, Wf, Wc, xdim, Y, hid);
}

extern "C" void kernel_launch(void* const* d_in, const int* in_sizes, int n_in,
                              void* d_out, int out_size)
{
    (void)in_sizes; (void)n_in; (void)out_size;
    const float* x   = (const float*)d_in[0];
    const float* Wf1 = (const float*)d_in[1];
    const float* bf1 = (const float*)d_in[2];
    const float* Wc1 = (const float*)d_in[3];
    const float* bc1 = (const float*)d_in[4];
    const float* Wf2 = (const float*)d_in[5];
    const float* bf2 = (const float*)d_in[6];
    const float* Wc2 = (const float*)d_in[7];
    const float* bc2 = (const float*)d_in[8];

    float* out = (float*)d_out;
    float* y2  = out;                       // [B, T, H]
    float* hid = out + (size_t)YSZ;         // [2, B, H]

    float* G;  cudaGetSymbolAddress((void**)&G,  g_G);
    float* y1; cudaGetSymbolAddress((void**)&y1, g_y1);

    cudaFuncSetAttribute(rec_kernel, cudaFuncAttributeMaxDynamicSharedMemorySize, WSM_BYTES);

    dim3 ggrid(4, (BB * TT) / GM_BM);
    dim3 gblk(256);

    // Layer 1
    gemm_gates<<<ggrid, gblk>>>(x, II, II, Wf1, Wc1, bf1, bc1, G);
    launch_rec(G, Wf1, Wc1, II, y1, hid);
    // Layer 2
    gemm_gates<<<ggrid, gblk>>>(y1, HH, HH, Wf2, Wc2, bf2, bc2, G);
    launch_rec(G, Wf2, Wc2, HH, y2, hid + (size_t)BB * HH);
}